// round 1
// baseline (speedup 1.0000x reference)
#include <cuda_runtime.h>
#include <cuda_bf16.h>
#include <math.h>

// Problem constants (fixed by the reference)
#define NUM_NODES   100000
#define NUM_EDGES   1600000
#define EMBED_DIM   128
#define NUM_CLASSES 2
#define NUM_LAYERS  3

// Scratch: __device__ globals (no allocations allowed).
// float2 layout: per-node pair of class features. Naturally 8B aligned.
__device__ float2 d_y [NUM_NODES];   // y = emb[idx] @ W
__device__ float2 d_p1[NUM_NODES];   // A y
__device__ float2 d_p2[NUM_NODES];   // A^2 y
__device__ float2 d_p3[NUM_NODES];   // A^3 y
__device__ float  d_a[NUM_LAYERS + 1]; // softmax(alpha)

// ---------------------------------------------------------------------------
// K0: softmax over the 4 alphas (single thread — trivial)
// ---------------------------------------------------------------------------
__global__ void softmax_alpha_kernel(const float* __restrict__ alpha) {
    float m = alpha[0];
    #pragma unroll
    for (int i = 1; i < NUM_LAYERS + 1; i++) m = fmaxf(m, alpha[i]);
    float s = 0.f;
    float e[NUM_LAYERS + 1];
    #pragma unroll
    for (int i = 0; i < NUM_LAYERS + 1; i++) { e[i] = expf(alpha[i] - m); s += e[i]; }
    float inv = 1.f / s;
    #pragma unroll
    for (int i = 0; i < NUM_LAYERS + 1; i++) d_a[i] = e[i] * inv;
}

// ---------------------------------------------------------------------------
// K1: y[n] = embedding[node_indices[n]] @ W    (one warp per node)
//     Also zero-initializes the three propagation buffers.
// W: [128, 2] row-major. Staged into shared split by class column so each
// lane does a conflict-free 128-bit LDS.
// ---------------------------------------------------------------------------
__global__ void __launch_bounds__(256)
gemv_kernel(const int*   __restrict__ node_indices,
            const float* __restrict__ embedding,
            const float* __restrict__ W) {
    __shared__ float sW0[EMBED_DIM];
    __shared__ float sW1[EMBED_DIM];
    int t = threadIdx.x;
    if (t < EMBED_DIM) {
        sW0[t] = W[2 * t + 0];
        sW1[t] = W[2 * t + 1];
    }
    __syncthreads();

    int gtid = blockIdx.x * blockDim.x + threadIdx.x;

    // Zero prop buffers (grid comfortably covers NUM_NODES)
    if (gtid < NUM_NODES) {
        float2 z = make_float2(0.f, 0.f);
        d_p1[gtid] = z; d_p2[gtid] = z; d_p3[gtid] = z;
    }

    int warp = gtid >> 5;
    int lane = gtid & 31;
    if (warp >= NUM_NODES) return;

    int nid = node_indices[warp];
    const float4* erow = reinterpret_cast<const float4*>(embedding + (size_t)nid * EMBED_DIM);
    float4 e = erow[lane];                              // 128B coalesced per warp
    const float4* w0 = reinterpret_cast<const float4*>(sW0);
    const float4* w1 = reinterpret_cast<const float4*>(sW1);
    float4 a0 = w0[lane];
    float4 a1 = w1[lane];

    float s0 = e.x * a0.x + e.y * a0.y + e.z * a0.z + e.w * a0.w;
    float s1 = e.x * a1.x + e.y * a1.y + e.z * a1.z + e.w * a1.w;

    #pragma unroll
    for (int off = 16; off > 0; off >>= 1) {
        s0 += __shfl_xor_sync(0xFFFFFFFFu, s0, off);
        s1 += __shfl_xor_sync(0xFFFFFFFFu, s1, off);
    }
    if (lane == 0) d_y[warp] = make_float2(s0, s1);
}

// ---------------------------------------------------------------------------
// K2..K4: SpMM in D=2. Thread per edge: nxt[row] += val * cur[col].
// cur ([100K,2] = 800 KB) is L2-resident; scatter uses spread-address
// float atomics (RED fast path in L2).
// ---------------------------------------------------------------------------
__global__ void __launch_bounds__(256)
spmm_kernel(const int*   __restrict__ adj_row,
            const int*   __restrict__ adj_col,
            const float* __restrict__ adj_val,
            const float2* __restrict__ cur,
            float2*       __restrict__ nxt) {
    int e = blockIdx.x * blockDim.x + threadIdx.x;
    if (e >= NUM_EDGES) return;
    int   r = adj_row[e];
    int   c = adj_col[e];
    float v = adj_val[e];
    float2 x = __ldg(&cur[c]);
    atomicAdd(&nxt[r].x, v * x.x);
    atomicAdd(&nxt[r].y, v * x.y);
}

// ---------------------------------------------------------------------------
// K5: out[n] = a0*y + a1*p1 + a2*p2 + a3*p3 + b
// ---------------------------------------------------------------------------
__global__ void __launch_bounds__(256)
combine_kernel(const float* __restrict__ b, float2* __restrict__ out) {
    int n = blockIdx.x * blockDim.x + threadIdx.x;
    if (n >= NUM_NODES) return;
    float a0 = d_a[0], a1 = d_a[1], a2 = d_a[2], a3 = d_a[3];
    float2 y  = d_y[n];
    float2 p1 = d_p1[n];
    float2 p2 = d_p2[n];
    float2 p3 = d_p3[n];
    float2 o;
    o.x = a0 * y.x + a1 * p1.x + a2 * p2.x + a3 * p3.x + b[0];
    o.y = a0 * y.y + a1 * p1.y + a2 * p2.y + a3 * p3.y + b[1];
    out[n] = o;
}

// ---------------------------------------------------------------------------
// Launch: inputs per metadata order:
// 0 node_indices(int32) 1 adj_row(int32) 2 adj_col(int32) 3 adj_val(f32)
// 4 embedding(f32) 5 alpha(f32) 6 W(f32) 7 b(f32)
// ---------------------------------------------------------------------------
extern "C" void kernel_launch(void* const* d_in, const int* in_sizes, int n_in,
                              void* d_out, int out_size) {
    const int*   node_indices = (const int*)  d_in[0];
    const int*   adj_row      = (const int*)  d_in[1];
    const int*   adj_col      = (const int*)  d_in[2];
    const float* adj_val      = (const float*)d_in[3];
    const float* embedding    = (const float*)d_in[4];
    const float* alpha        = (const float*)d_in[5];
    const float* W            = (const float*)d_in[6];
    const float* b            = (const float*)d_in[7];
    float2* out = (float2*)d_out;

    // Resolve device-global addresses once per launch (host-side, capturable)
    float2 *p_y, *p_p1, *p_p2, *p_p3;
    cudaGetSymbolAddress((void**)&p_y,  d_y);
    cudaGetSymbolAddress((void**)&p_p1, d_p1);
    cudaGetSymbolAddress((void**)&p_p2, d_p2);
    cudaGetSymbolAddress((void**)&p_p3, d_p3);

    softmax_alpha_kernel<<<1, 1>>>(alpha);

    // one warp per node -> 8 nodes per 256-thread block
    int gemv_blocks = (NUM_NODES + 7) / 8;
    gemv_kernel<<<gemv_blocks, 256>>>(node_indices, embedding, W);

    int spmm_blocks = (NUM_EDGES + 255) / 256;
    spmm_kernel<<<spmm_blocks, 256>>>(adj_row, adj_col, adj_val, p_y,  p_p1);
    spmm_kernel<<<spmm_blocks, 256>>>(adj_row, adj_col, adj_val, p_p1, p_p2);
    spmm_kernel<<<spmm_blocks, 256>>>(adj_row, adj_col, adj_val, p_p2, p_p3);

    int comb_blocks = (NUM_NODES + 255) / 256;
    combine_kernel<<<comb_blocks, 256>>>(b, out);
}

// round 4
// speedup vs baseline: 1.3038x; 1.3038x over previous
#include <cuda_runtime.h>
#include <cuda_bf16.h>
#include <math.h>

// Problem constants (fixed by the reference)
#define NUM_NODES   100000
#define NUM_EDGES   1600000
#define EMBED_DIM   128
#define NUM_CLASSES 2
#define NUM_LAYERS  3

#define EDGES_PER_THREAD 4

// Scratch: __device__ globals (no allocations allowed).
__device__ float2 d_y [NUM_NODES];   // y = emb[idx] @ W
__device__ float2 d_p1[NUM_NODES];   // A y
__device__ float2 d_p2[NUM_NODES];   // A^2 y
__device__ float2 d_p3[NUM_NODES];   // A^3 y
__device__ float  d_a[NUM_LAYERS + 1]; // softmax(alpha)

// One 64-bit vector reduction per edge (red = no return value -> REDG fast
// path in L2). Inline PTX so we don't depend on header intrinsic availability.
__device__ __forceinline__ void red_add_f2(float2* addr, float vx, float vy) {
    asm volatile("red.global.add.v2.f32 [%0], {%1, %2};"
                 :: "l"(addr), "f"(vx), "f"(vy) : "memory");
}

// ---------------------------------------------------------------------------
// K0: softmax over the 4 alphas (single thread — trivial)
// ---------------------------------------------------------------------------
__global__ void softmax_alpha_kernel(const float* __restrict__ alpha) {
    float m = alpha[0];
    #pragma unroll
    for (int i = 1; i < NUM_LAYERS + 1; i++) m = fmaxf(m, alpha[i]);
    float s = 0.f;
    float e[NUM_LAYERS + 1];
    #pragma unroll
    for (int i = 0; i < NUM_LAYERS + 1; i++) { e[i] = expf(alpha[i] - m); s += e[i]; }
    float inv = 1.f / s;
    #pragma unroll
    for (int i = 0; i < NUM_LAYERS + 1; i++) d_a[i] = e[i] * inv;
}

// ---------------------------------------------------------------------------
// K1: y[n] = embedding[node_indices[n]] @ W    (one warp per node)
//     Also zero-initializes the three propagation buffers.
// ---------------------------------------------------------------------------
__global__ void __launch_bounds__(256)
gemv_kernel(const int*   __restrict__ node_indices,
            const float* __restrict__ embedding,
            const float* __restrict__ W) {
    __shared__ float sW0[EMBED_DIM];
    __shared__ float sW1[EMBED_DIM];
    int t = threadIdx.x;
    if (t < EMBED_DIM) {
        sW0[t] = W[2 * t + 0];
        sW1[t] = W[2 * t + 1];
    }
    __syncthreads();

    int gtid = blockIdx.x * blockDim.x + threadIdx.x;

    // Zero prop buffers (grid comfortably covers NUM_NODES)
    if (gtid < NUM_NODES) {
        float2 z = make_float2(0.f, 0.f);
        d_p1[gtid] = z; d_p2[gtid] = z; d_p3[gtid] = z;
    }

    int warp = gtid >> 5;
    int lane = gtid & 31;
    if (warp >= NUM_NODES) return;

    int nid = node_indices[warp];
    const float4* erow = reinterpret_cast<const float4*>(embedding + (size_t)nid * EMBED_DIM);
    float4 e = erow[lane];                              // 128B coalesced per warp
    const float4* w0 = reinterpret_cast<const float4*>(sW0);
    const float4* w1 = reinterpret_cast<const float4*>(sW1);
    float4 a0 = w0[lane];
    float4 a1 = w1[lane];

    float s0 = e.x * a0.x + e.y * a0.y + e.z * a0.z + e.w * a0.w;
    float s1 = e.x * a1.x + e.y * a1.y + e.z * a1.z + e.w * a1.w;

    #pragma unroll
    for (int off = 16; off > 0; off >>= 1) {
        s0 += __shfl_xor_sync(0xFFFFFFFFu, s0, off);
        s1 += __shfl_xor_sync(0xFFFFFFFFu, s1, off);
    }
    if (lane == 0) d_y[warp] = make_float2(s0, s1);
}

// ---------------------------------------------------------------------------
// K2..K4: SpMM in D=2. Each thread handles 4 edges:
//   - int4/float4 vector loads of row/col/val (coalesced, L2-resident)
//   - 4 independent float2 gathers batched for MLP
//   - ONE red.global.add.v2.f32 per edge instead of two scalar atomics
//     -> halves L2 atomic-ALU transactions, no return-value round trip.
// NUM_EDGES divisible by 4 -> vector loads always in-bounds.
// ---------------------------------------------------------------------------
__global__ void __launch_bounds__(256)
spmm_kernel(const int*   __restrict__ adj_row,
            const int*   __restrict__ adj_col,
            const float* __restrict__ adj_val,
            const float2* __restrict__ cur,
            float2*       __restrict__ nxt) {
    int q = blockIdx.x * blockDim.x + threadIdx.x;   // quad index
    if (q >= NUM_EDGES / EDGES_PER_THREAD) return;

    int4   r4 = reinterpret_cast<const int4*>(adj_row)[q];
    int4   c4 = reinterpret_cast<const int4*>(adj_col)[q];
    float4 v4 = reinterpret_cast<const float4*>(adj_val)[q];

    // Batch the 4 random gathers first (independent -> overlapped in flight)
    float2 x0 = __ldg(&cur[c4.x]);
    float2 x1 = __ldg(&cur[c4.y]);
    float2 x2 = __ldg(&cur[c4.z]);
    float2 x3 = __ldg(&cur[c4.w]);

    red_add_f2(&nxt[r4.x], v4.x * x0.x, v4.x * x0.y);
    red_add_f2(&nxt[r4.y], v4.y * x1.x, v4.y * x1.y);
    red_add_f2(&nxt[r4.z], v4.z * x2.x, v4.z * x2.y);
    red_add_f2(&nxt[r4.w], v4.w * x3.x, v4.w * x3.y);
}

// ---------------------------------------------------------------------------
// K5: out[n] = a0*y + a1*p1 + a2*p2 + a3*p3 + b
// ---------------------------------------------------------------------------
__global__ void __launch_bounds__(256)
combine_kernel(const float* __restrict__ b, float2* __restrict__ out) {
    int n = blockIdx.x * blockDim.x + threadIdx.x;
    if (n >= NUM_NODES) return;
    float a0 = d_a[0], a1 = d_a[1], a2 = d_a[2], a3 = d_a[3];
    float2 y  = d_y[n];
    float2 p1 = d_p1[n];
    float2 p2 = d_p2[n];
    float2 p3 = d_p3[n];
    float2 o;
    o.x = a0 * y.x + a1 * p1.x + a2 * p2.x + a3 * p3.x + b[0];
    o.y = a0 * y.y + a1 * p1.y + a2 * p2.y + a3 * p3.y + b[1];
    out[n] = o;
}

// ---------------------------------------------------------------------------
// Launch: inputs per metadata order:
// 0 node_indices(int32) 1 adj_row(int32) 2 adj_col(int32) 3 adj_val(f32)
// 4 embedding(f32) 5 alpha(f32) 6 W(f32) 7 b(f32)
// ---------------------------------------------------------------------------
extern "C" void kernel_launch(void* const* d_in, const int* in_sizes, int n_in,
                              void* d_out, int out_size) {
    const int*   node_indices = (const int*)  d_in[0];
    const int*   adj_row      = (const int*)  d_in[1];
    const int*   adj_col      = (const int*)  d_in[2];
    const float* adj_val      = (const float*)d_in[3];
    const float* embedding    = (const float*)d_in[4];
    const float* alpha        = (const float*)d_in[5];
    const float* W            = (const float*)d_in[6];
    const float* b            = (const float*)d_in[7];
    float2* out = (float2*)d_out;

    float2 *p_y, *p_p1, *p_p2, *p_p3;
    cudaGetSymbolAddress((void**)&p_y,  d_y);
    cudaGetSymbolAddress((void**)&p_p1, d_p1);
    cudaGetSymbolAddress((void**)&p_p2, d_p2);
    cudaGetSymbolAddress((void**)&p_p3, d_p3);

    softmax_alpha_kernel<<<1, 1>>>(alpha);

    int gemv_blocks = (NUM_NODES + 7) / 8;     // one warp per node
    gemv_kernel<<<gemv_blocks, 256>>>(node_indices, embedding, W);

    int quads = NUM_EDGES / EDGES_PER_THREAD;
    int spmm_blocks = (quads + 255) / 256;
    spmm_kernel<<<spmm_blocks, 256>>>(adj_row, adj_col, adj_val, p_y,  p_p1);
    spmm_kernel<<<spmm_blocks, 256>>>(adj_row, adj_col, adj_val, p_p1, p_p2);
    spmm_kernel<<<spmm_blocks, 256>>>(adj_row, adj_col, adj_val, p_p2, p_p3);

    int comb_blocks = (NUM_NODES + 255) / 256;
    combine_kernel<<<comb_blocks, 256>>>(b, out);
}